// round 16
// baseline (speedup 1.0000x reference)
#include <cuda_runtime.h>
#include <cstddef>

typedef unsigned long long ull;

// ================= scratch (device globals; no allocations) =================
__device__ float g_F[4 * 17 * 4096];         // [b][j][m]
__device__ float g_WhT[7 * 1024 * 512];      // [u][co][ho]
__device__ float g_Vp[64 * 4 * 9 * 1024];    // [chunk][t][9 rows: own-group 8 + bias][co]
__device__ float g_V[4 * 17 * 1024];         // [t][j][co]
__device__ float g_Gp[8 * 28 * 17 * 512];    // [cs][pair (s-grouped)][j][ho]
__device__ float g_K[10 * 17 * 512];         // [s][j][ho], s = u+t tap index
__device__ float g_clo[4 * 1024];            // f[b,0,:]*V3 + b_up
__device__ float g_chi[4 * 1024];            // f[b,4095,:]*V0 + b_up
__device__ float g_c9p[8 * 7 * 9 * 512];     // [cs][u][k9][ho]

// pair indexing: pairs (u,t) sorted by s=u+t; pidx[u][t] = flat index
__constant__ int c_pidx[7][4] = {
  {0,1,3,6},{2,4,7,10},{5,8,11,14},{9,12,15,18},
  {13,16,19,22},{17,20,23,25},{21,24,26,27}};
__constant__ int c_pstart[10] = {0,1,3,6,10,14,18,22,25,27};
__constant__ int c_np[10]     = {1,2,3,4,4,4,4,3,2,1};

// boundary columns and their spurious-term tables
__constant__ int c_ncorr[6] = {3,2,1, 1,2,3};
__constant__ int c_fu[6][3] = {{0,1,2},{0,1,0},{0,0,0},{6,0,0},{5,6,0},{4,5,6}};
__constant__ int c_fs[6][3] = {{0,0,1},{0,1,0},{1,0,0},{2,0,0},{2,0,0},{2,0,0}}; // 0=b_up 1=clo 2=chi

__device__ __forceinline__ void ffma2(ull &d, const ull a, const ull b) {
    asm("fma.rn.f32x2 %0, %1, %2, %0;" : "+l"(d) : "l"(a), "l"(b));
}
__device__ __forceinline__ float2 u2f(ull v) {
    float2 r; asm("mov.b64 {%0,%1}, %2;" : "=f"(r.x), "=f"(r.y) : "l"(v)); return r;
}
__device__ __forceinline__ ull dup2(float v) {
    ull r; asm("mov.b64 %0, {%1,%1};" : "=l"(r) : "f"(v)); return r;
}

// ================= kA: F + WhT + Vp (independent stage-1 work) =================
__global__ void __launch_bounds__(256) kA(const void* idxraw, const float* __restrict__ cb,
                                          const float* __restrict__ sc,
                                          const float* __restrict__ Wh,
                                          const float* __restrict__ W_out,
                                          const float* __restrict__ b_out,
                                          const float* __restrict__ W_up) {
    __shared__ __align__(16) float su[7392];
    int bid = blockIdx.x, tid = threadIdx.x;

    if (bid < 128) {
        // ---- F[b][j][m] with inline int64/int32 detection ----
        const unsigned* w = (const unsigned*)idxraw;
        unsigned v = w[2 * tid + 1];
        int ok = (v == 0u) || (v == 0xFFFFFFFFu);
        int is64 = __syncthreads_and(ok);
        if (tid < 128) su[tid] = sc[tid];
        __syncthreads();
        int gt = bid * 256 + tid;
        int m = gt & 4095, gb = (gt >> 12) & 1, b = gt >> 13;
        float acc[8];
#pragma unroll
        for (int j = 0; j < 8; ++j) acc[j] = 0.f;
#pragma unroll
        for (int qq = 0; qq < 8; ++qq) {
            int gq = gb * 8 + qq;
            size_t off = (size_t)(b * 16 + gq) * 4096 + m;
            long long c;
            if (is64) c = ((const long long*)idxraw)[off];
            else      c = ((const int*)idxraw)[off];
            if (c >= 0) {
                const float4* row = (const float4*)(cb + ((size_t)gq * 1024 + (int)c) * 8);
                float4 r0 = row[0], r1 = row[1];
                const float* s = &su[gq * 8];
                acc[0] += r0.x*s[0]; acc[1] += r0.y*s[1];
                acc[2] += r0.z*s[2]; acc[3] += r0.w*s[3];
                acc[4] += r1.x*s[4]; acc[5] += r1.y*s[5];
                acc[6] += r1.z*s[6]; acc[7] += r1.w*s[7];
            }
        }
#pragma unroll
        for (int j = 0; j < 8; ++j)
            g_F[((size_t)b * 17 + gb * 8 + j) * 4096 + m] = acc[j];
        if (gb == 0) g_F[((size_t)b * 17 + 16) * 4096 + m] = 1.0f;

    } else if (bid < 640) {
        // ---- tiled transpose W_head [ho][co][u] -> WhT[u][co][ho] ----
        int t = bid - 128;
        int co0 = (t & 31) * 32, ho0 = (t >> 5) * 32;
        for (int p = tid; p < 1024; p += 256) {
            int ho_l = p >> 5, co_l = p & 31;
            const float* src = Wh + ((size_t)(ho0 + ho_l) * 1024 + co0 + co_l) * 7;
#pragma unroll
            for (int u = 0; u < 7; ++u) su[(u * 32 + co_l) * 33 + ho_l] = src[u];
        }
        __syncthreads();
        for (int p = tid; p < 7168; p += 256) {
            int u = p >> 10, r = p & 1023, co_l = r >> 5, ho_l = r & 31;
            g_WhT[((size_t)u * 1024 + co0 + co_l) * 512 + ho0 + ho_l] = su[(u * 32 + co_l) * 33 + ho_l];
        }

    } else {
        // ---- Vp[chunk][t][9][co]: partial over 16-wide c-chunk of P[j][c]*W_up[c][co][t]
        int t = bid - 640;                 // 256 blocks
        int cotile = t & 3, chunk = t >> 2; // chunk in [0,64)
        int co = cotile * 256 + tid;
        int g = chunk >> 5;
        int ebase = chunk * 16 - g * 512;
        if (tid < 144) {
            if (tid < 128) {
                int d = tid >> 4, ii = tid & 15;
                su[d * 16 + ii] = W_out[((size_t)(g * 8 + d)) * 512 + ebase + ii];
            } else {
                su[128 + (tid - 128)] = b_out[g * 512 + ebase + (tid - 128)];
            }
        }
        __syncthreads();
        float acc[4][9];
#pragma unroll
        for (int tt = 0; tt < 4; ++tt)
#pragma unroll
            for (int d = 0; d < 9; ++d) acc[tt][d] = 0.f;
#pragma unroll
        for (int i = 0; i < 16; ++i) {
            int c = chunk * 16 + i;
            float4 w4 = *(const float4*)&W_up[((size_t)c * 1024 + co) * 4];
            float wt[4] = {w4.x, w4.y, w4.z, w4.w};
#pragma unroll
            for (int d = 0; d < 8; ++d) {
                float p = su[d * 16 + i];
#pragma unroll
                for (int tt = 0; tt < 4; ++tt) acc[tt][d] += p * wt[tt];
            }
            float pb = su[128 + i];
#pragma unroll
            for (int tt = 0; tt < 4; ++tt) acc[tt][8] += pb * wt[tt];
        }
#pragma unroll
        for (int tt = 0; tt < 4; ++tt) {
#pragma unroll
            for (int d = 0; d < 8; ++d)
                g_Vp[(((size_t)chunk * 4 + tt) * 9 + d) * 1024 + co] = acc[tt][d];
            g_Vp[(((size_t)chunk * 4 + tt) * 9 + 8) * 1024 + co] = acc[tt][8];
        }
    }
}

// ================= kB: Vred (group-aware) =================
__global__ void __launch_bounds__(256) kB() {
    int idx = blockIdx.x * 256 + threadIdx.x;   // < 69632
    int row = idx >> 10, co = idx & 1023;
    int t = row / 17, j = row - t * 17;
    float s = 0.f;
    if (j == 16) {
#pragma unroll
        for (int cs = 0; cs < 64; ++cs)
            s += g_Vp[(((size_t)cs * 4 + t) * 9 + 8) * 1024 + co];
    } else if (j < 8) {
#pragma unroll
        for (int cs = 0; cs < 32; ++cs)
            s += g_Vp[(((size_t)cs * 4 + t) * 9 + j) * 1024 + co];
    } else {
#pragma unroll
        for (int cs = 32; cs < 64; ++cs)
            s += g_Vp[(((size_t)cs * 4 + t) * 9 + (j - 8)) * 1024 + co];
    }
    g_V[idx] = s;
}

// ================= kC: G-GEMM (f32x2-packed; 28 (u,t) pairs, s-grouped out) + corr1 ====
__global__ void __launch_bounds__(128) kC(const float* __restrict__ b_up) {
    __shared__ __align__(16) float sV2[128 * 80];   // [c][t*20 + j], 40KB
    int tid = threadIdx.x, bid = blockIdx.x;
    if (bid < 448) {
        int cs  = bid & 7;
        int hot = (bid >> 3) & 7;
        int u   = bid >> 6;              // 0..6
        int c0 = cs * 128, hb = hot * 64;
        int ho_l = tid & 31, rg = tid >> 5;   // rg = t
        for (int i = tid; i < 68 * 128; i += 128) {
            int row = i >> 7, c = i & 127;     // row = t*17+j
            int t = row / 17, j = row - t * 17;
            sV2[c * 80 + t * 20 + j] = g_V[(size_t)row * 1024 + c0 + c];
        }
        __syncthreads();
        ull acc2[9][2];
#pragma unroll
        for (int jj = 0; jj < 9; ++jj) { acc2[jj][0] = 0ull; acc2[jj][1] = 0ull; }
        const float* Wp = g_WhT + ((size_t)u * 1024 + c0) * 512 + hb + ho_l;
#pragma unroll 4
        for (int c = 0; c < 128; ++c) {
            float b0 = __ldg(&Wp[(size_t)c * 512]);
            float b1 = __ldg(&Wp[(size_t)c * 512 + 32]);
            ull b0d = dup2(b0), b1d = dup2(b1);
            const ull* av2 = (const ull*)&sV2[c * 80 + rg * 20];
#pragma unroll
            for (int jj = 0; jj < 9; ++jj) {
                ull av = av2[jj];
                ffma2(acc2[jj][0], av, b0d);
                ffma2(acc2[jj][1], av, b1d);
            }
        }
        int pidx = c_pidx[u][rg];
        float* gp = g_Gp + ((size_t)(cs * 28 + pidx) * 17) * 512 + hb + ho_l;
#pragma unroll
        for (int jj = 0; jj < 8; ++jj) {
            float2 x0 = u2f(acc2[jj][0]);
            float2 x1 = u2f(acc2[jj][1]);
            gp[(size_t)(2 * jj) * 512]          = x0.x;
            gp[(size_t)(2 * jj) * 512 + 32]     = x1.x;
            gp[(size_t)(2 * jj + 1) * 512]      = x0.y;
            gp[(size_t)(2 * jj + 1) * 512 + 32] = x1.y;
        }
        {
            float2 x0 = u2f(acc2[8][0]);
            float2 x1 = u2f(acc2[8][1]);
            gp[(size_t)16 * 512]      = x0.x;
            gp[(size_t)16 * 512 + 32] = x1.x;
        }
    } else {
        // corr1: 64 blocks of 128 threads
        int q = bid - 448;
        int b = q >> 4, r2 = q & 15, hi = r2 >> 3, cotile = r2 & 7;
        int co = cotile * 128 + tid;
        int frame = hi ? 4095 : 0;
        int t = hi ? 0 : 3;
        float acc = b_up[co];
#pragma unroll
        for (int j = 0; j < 17; ++j)
            acc += g_F[((size_t)b * 17 + j) * 4096 + frame] * g_V[((size_t)t * 17 + j) * 1024 + co];
        if (hi) g_chi[b * 1024 + co] = acc; else g_clo[b * 1024 + co] = acc;
    }
}

// ================= kD: K reduce (contiguous s-groups) + C9 (4x parallel) =========
__global__ void __launch_bounds__(512) kD(const float* __restrict__ b_up) {
    __shared__ float scoef[9][128];      // 4.6KB
    __shared__ float sred[4][9][128];    // 18KB
    int bid = blockIdx.x, tid = threadIdx.x;
    if (bid < 170) {
        int idx = bid * 512 + tid;     // 87040 exactly; s uniform per block
        int s = idx / 8704;
        int rem = idx - s * 8704;
        int p0 = c_pstart[s], np = c_np[s];
        float acc = 0.f;
#pragma unroll
        for (int p = 0; p < 4; ++p) {
            if (p < np) {
                size_t base = (size_t)(p0 + p) * 8704 + rem;
#pragma unroll
                for (int cs = 0; cs < 8; ++cs)
                    acc += g_Gp[(size_t)cs * (28 * 8704) + base];
            }
        }
        g_K[idx] = acc;
    } else {
        // C9: 224 blocks = u(7) x hot(4) x cq(8); 512 threads, csub covers 32 c's
        int v = bid - 170;
        int u = v >> 5, rem = v & 31;
        int hot = rem & 3, cq = rem >> 2;         // cq in [0,8)
        int hb = hot * 128;
        int ho_l = tid & 127, csub = tid >> 7;    // csub in [0,4)
        int cbase = cq * 128;
        for (int i = tid; i < 9 * 128; i += 512) {
            int k = i / 128, c = i & 127;
            int cg = cbase + c;
            float val;
            if (k == 0)      val = b_up[cg];
            else if (k < 5)  val = g_clo[(k - 1) * 1024 + cg];
            else             val = g_chi[(k - 5) * 1024 + cg];
            scoef[k][c] = val;
        }
        __syncthreads();
        int c0 = cbase + csub * 32;
        float acc[9];
#pragma unroll
        for (int k = 0; k < 9; ++k) acc[k] = 0.f;
        const float* W = g_WhT + ((size_t)u * 1024 + c0) * 512 + hb + ho_l;
#pragma unroll
        for (int cc = 0; cc < 32; ++cc) {
            float w = __ldg(&W[(size_t)cc * 512]);
#pragma unroll
            for (int k = 0; k < 9; ++k) acc[k] += scoef[k][csub * 32 + cc] * w;
        }
#pragma unroll
        for (int k = 0; k < 9; ++k) sred[csub][k][ho_l] = acc[k];
        __syncthreads();
        if (csub == 0) {
#pragma unroll
            for (int k = 0; k < 9; ++k) {
                float s = sred[0][k][ho_l] + sred[1][k][ho_l]
                        + sred[2][k][ho_l] + sred[3][k][ho_l];
                g_c9p[(((size_t)cq * 7 + u) * 9 + k) * 512 + hb + ho_l] = s;
            }
        }
    }
}

// ================= kE: main GEMM (f32x2), 64m x 128ho tile, batch-looped =========
// grid (64,4,1): sB/sFB2 loaded once, reused across all 4 batches (b-loop in block).
// smem: sB [2*80*128]f @0 (81920B), sA2 [16*96]float2 @81920 (12288B), sFB2 [2*128]f @94208
__global__ void __launch_bounds__(256, 2) kE(float* __restrict__ out,
                                             const float* __restrict__ b_head) {
    extern __shared__ __align__(16) char smem_raw[];
    float*  sB   = (float*)smem_raw;                        // [r*80 + dm*16 + j][128]
    float2* sA2  = (float2*)(smem_raw + 81920);             // [j<16][96]
    float*  sFB2 = (float*)(smem_raw + 81920 + 12288);      // [r][128]
    int tid = threadIdx.x;
    int mb = blockIdx.x * 64;
    int hb = blockIdx.y * 128;
#pragma unroll 4
    for (int i = tid; i < 2 * 80 * 128; i += 256) {
        int q = i >> 7, hol = i & 127;
        int r = (q >= 80);
        int dmj = q - 80 * r;
        int dm = dmj >> 4, j = dmj & 15;
        int s = 2 * dm + (r ? 0 : 1);
        sB[i] = g_K[((size_t)(s * 17 + j)) * 512 + hb + hol];
    }
    // per-r fullbias: b_head + C9(k=0) + folded j=16 taps
    {
        int r = tid >> 7, hol = tid & 127;
        float s = b_head[hb + hol];
#pragma unroll
        for (int cs = 0; cs < 8; ++cs)
#pragma unroll
            for (int u = 0; u < 7; ++u)
                s += g_c9p[(((size_t)cs * 7 + u) * 9) * 512 + hb + hol];
#pragma unroll
        for (int dm = 0; dm < 5; ++dm) {
            int sv = 2 * dm + (r ? 0 : 1);
            s += g_K[((size_t)(sv * 17 + 16)) * 512 + hb + hol];
        }
        sFB2[r * 128 + hol] = s;
    }

    int tho = tid & 31, tm = tid >> 5;
    const ull* uA = ((const ull*)sA2) + (size_t)tm * 12;
    const ull* uB = (const ull*)sB;     // rows of 64 ull (128 floats)

    for (int b = 0; b < 4; ++b) {
        __syncthreads();   // previous iteration's readers done (and first: orders nothing harmful)
        for (int i = tid; i < 16 * 96; i += 256) {
            int j = i / 96, r = i % 96, tmw = r / 12, k = r % 12;
            int m = mb + tmw * 8 + k - 2;
            float v = (m >= 0 && m < 4096) ? g_F[((size_t)b * 17 + j) * 4096 + m] : 0.f;
            sA2[i] = make_float2(v, v);
        }
        __syncthreads();   // sA2 (and on b=0, sB/sFB2) visible

        ull acc[2][2][8];
#pragma unroll
        for (int r = 0; r < 2; ++r)
#pragma unroll
            for (int h = 0; h < 2; ++h)
#pragma unroll
                for (int mi = 0; mi < 8; ++mi) acc[r][h][mi] = 0ull;

        for (int j = 0; j < 16; ++j) {
            ull a[12];
#pragma unroll
            for (int k = 0; k < 12; ++k) a[k] = uA[j * 96 + k];
#pragma unroll
            for (int dm = 0; dm < 5; ++dm) {
                int row0 = (dm * 16 + j) * 64;
                int row1 = (80 + dm * 16 + j) * 64;
                ull b00 = uB[row0 + tho];
                ull b01 = uB[row0 + 32 + tho];
                ull b10 = uB[row1 + tho];
                ull b11 = uB[row1 + 32 + tho];
#pragma unroll
                for (int mi = 0; mi < 8; ++mi) {
                    ull av = a[mi + dm];
                    ffma2(acc[0][0][mi], av, b00);
                    ffma2(acc[0][1][mi], av, b01);
                    ffma2(acc[1][0][mi], av, b10);
                    ffma2(acc[1][1][mi], av, b11);
                }
            }
        }

        int nb = 2 * (mb + tm * 8);
#pragma unroll
        for (int h = 0; h < 2; ++h) {
            int hoA = hb + h * 64 + 2 * tho;
            float fbA0 = sFB2[h * 64 + 2 * tho];            // r=0, ho lane 0
            float fbA1 = sFB2[h * 64 + 2 * tho + 1];        // r=0, ho lane 1
            float fbB0 = sFB2[128 + h * 64 + 2 * tho];      // r=1, ho lane 0
            float fbB1 = sFB2[128 + h * 64 + 2 * tho + 1];  // r=1, ho lane 1
            float r0[16], r1[16];
#pragma unroll
            for (int mi = 0; mi < 8; ++mi) {
                float2 x0 = u2f(acc[0][h][mi]);   // r=0: {hoA, hoA+1}
                float2 x1 = u2f(acc[1][h][mi]);   // r=1
                r0[2 * mi]     = x0.x + fbA0;
                r0[2 * mi + 1] = x1.x + fbB0;
                r1[2 * mi]     = x0.y + fbA1;
                r1[2 * mi + 1] = x1.y + fbB1;
            }

            if (blockIdx.x == 0 && tm == 0) {
                // C9 spurious-term fix (n = 0,1,2)
#pragma unroll
                for (int ni = 0; ni < 3; ++ni) {
                    float d0 = 0.f, d1 = 0.f;
                    int nt = c_ncorr[ni];
#pragma unroll
                    for (int k = 0; k < 3; ++k) {
                        if (k < nt) {
                            int u = c_fu[ni][k], src = c_fs[ni][k];
                            int kidx = (src == 0) ? 0 : (src == 1 ? 1 + b : 5 + b);
#pragma unroll
                            for (int cs = 0; cs < 8; ++cs) {
                                size_t o = (((size_t)cs * 7 + u) * 9 + kidx) * 512 + hoA;
                                d0 += g_c9p[o]; d1 += g_c9p[o + 1];
                            }
                        }
                    }
                    r0[ni] -= d0; r1[ni] -= d1;
                }
                // j16-fold missing-tap fix (window-clipped columns q=0..3)
                float K16_0a = g_K[(size_t)(0 * 17 + 16) * 512 + hoA], K16_0b = g_K[(size_t)(0 * 17 + 16) * 512 + hoA + 1];
                float K16_1a = g_K[(size_t)(1 * 17 + 16) * 512 + hoA], K16_1b = g_K[(size_t)(1 * 17 + 16) * 512 + hoA + 1];
                float K16_2a = g_K[(size_t)(2 * 17 + 16) * 512 + hoA], K16_2b = g_K[(size_t)(2 * 17 + 16) * 512 + hoA + 1];
                float K16_3a = g_K[(size_t)(3 * 17 + 16) * 512 + hoA], K16_3b = g_K[(size_t)(3 * 17 + 16) * 512 + hoA + 1];
                r0[0] -= K16_1a + K16_3a;  r1[0] -= K16_1b + K16_3b;   // m0=0, r=0
                r0[1] -= K16_0a + K16_2a;  r1[1] -= K16_0b + K16_2b;   // m0=0, r=1
                r0[2] -= K16_1a;           r1[2] -= K16_1b;            // m0=1, r=0
                r0[3] -= K16_0a;           r1[3] -= K16_0b;            // m0=1, r=1
            }
            if (blockIdx.x == 63 && tm == 7) {
                // C9 spurious-term fix (n = 8189,8190,8191)
#pragma unroll
                for (int ni = 3; ni < 6; ++ni) {
                    float d0 = 0.f, d1 = 0.f;
                    int nt = c_ncorr[ni];
#pragma unroll
                    for (int k = 0; k < 3; ++k) {
                        if (k < nt) {
                            int u = c_fu[ni][k], src = c_fs[ni][k];
                            int kidx = (src == 0) ? 0 : (src == 1 ? 1 + b : 5 + b);
#pragma unroll
                            for (int cs = 0; cs < 8; ++cs) {
                                size_t o = (((size_t)cs * 7 + u) * 9 + kidx) * 512 + hoA;
                                d0 += g_c9p[o]; d1 += g_c9p[o + 1];
                            }
                        }
                    }
                    r0[ni + 10] -= d0; r1[ni + 10] -= d1;
                }
                // j16-fold missing-tap fix (q=12..15 -> n=8188..8191)
                float K16_6a = g_K[(size_t)(6 * 17 + 16) * 512 + hoA], K16_6b = g_K[(size_t)(6 * 17 + 16) * 512 + hoA + 1];
                float K16_7a = g_K[(size_t)(7 * 17 + 16) * 512 + hoA], K16_7b = g_K[(size_t)(7 * 17 + 16) * 512 + hoA + 1];
                float K16_8a = g_K[(size_t)(8 * 17 + 16) * 512 + hoA], K16_8b = g_K[(size_t)(8 * 17 + 16) * 512 + hoA + 1];
                float K16_9a = g_K[(size_t)(9 * 17 + 16) * 512 + hoA], K16_9b = g_K[(size_t)(9 * 17 + 16) * 512 + hoA + 1];
                r0[12] -= K16_9a;           r1[12] -= K16_9b;           // m0=4094, r=0
                r0[13] -= K16_8a;           r1[13] -= K16_8b;           // m0=4094, r=1
                r0[14] -= K16_7a + K16_9a;  r1[14] -= K16_7b + K16_9b;  // m0=4095, r=0
                r0[15] -= K16_6a + K16_8a;  r1[15] -= K16_6b + K16_8b;  // m0=4095, r=1
            }

            float* p0 = out + ((size_t)b * 512 + hoA) * 8192 + nb;
            float* p1 = p0 + 8192;
#pragma unroll
            for (int s = 0; s < 4; ++s) {
                *(float4*)(p0 + 4 * s) = *(float4*)&r0[4 * s];
                *(float4*)(p1 + 4 * s) = *(float4*)&r1[4 * s];
            }
        }
    }
}

// ================= host =================
extern "C" void kernel_launch(void* const* d_in, const int* in_sizes, int n_in,
                              void* d_out, int out_size) {
    const void*  idx    = d_in[0];
    const float* cb     = (const float*)d_in[1];
    const float* sc     = (const float*)d_in[2];
    const float* W_out  = (const float*)d_in[3];
    const float* b_out  = (const float*)d_in[4];
    const float* W_up   = (const float*)d_in[5];
    const float* b_up   = (const float*)d_in[6];
    const float* W_head = (const float*)d_in[7];
    const float* b_head = (const float*)d_in[8];
    float* out = (float*)d_out;

    const int KE_SMEM = 81920 + 12288 + 1024;
    cudaFuncSetAttribute(kE, cudaFuncAttributeMaxDynamicSharedMemorySize, KE_SMEM);

    kA<<<896, 256>>>(idx, cb, sc, W_head, W_out, b_out, W_up);
    kB<<<272, 256>>>();
    kC<<<512, 128>>>(b_up);
    kD<<<394, 512>>>(b_up);
    kE<<<dim3(64, 4, 1), 256, KE_SMEM>>>(out, b_head);
}

// round 17
// speedup vs baseline: 1.0337x; 1.0337x over previous
#include <cuda_runtime.h>
#include <cstddef>

typedef unsigned long long ull;

// ================= scratch (device globals; no allocations) =================
__device__ float g_F[4 * 17 * 4096];         // [b][j][m]
__device__ float g_WhT[7 * 1024 * 512];      // [u][co][ho]
__device__ float g_Vp[64 * 4 * 9 * 1024];    // [chunk][t][9 rows: own-group 8 + bias][co]
__device__ float g_V[4 * 17 * 1024];         // [t][j][co]
__device__ float g_Gp[8 * 28 * 17 * 512];    // [cs][pair (s-grouped)][j][ho]
__device__ float g_K[10 * 17 * 512];         // [s][j][ho], s = u+t tap index
__device__ float g_clo[4 * 1024];            // f[b,0,:]*V3 + b_up
__device__ float g_chi[4 * 1024];            // f[b,4095,:]*V0 + b_up
__device__ float g_c9p[8 * 7 * 9 * 512];     // [cs][u][k9][ho]

// pair indexing: pairs (u,t) sorted by s=u+t; pidx[u][t] = flat index
__constant__ int c_pidx[7][4] = {
  {0,1,3,6},{2,4,7,10},{5,8,11,14},{9,12,15,18},
  {13,16,19,22},{17,20,23,25},{21,24,26,27}};
__constant__ int c_pstart[10] = {0,1,3,6,10,14,18,22,25,27};
__constant__ int c_np[10]     = {1,2,3,4,4,4,4,3,2,1};

// boundary columns and their spurious-term tables
__constant__ int c_ncorr[6] = {3,2,1, 1,2,3};
__constant__ int c_fu[6][3] = {{0,1,2},{0,1,0},{0,0,0},{6,0,0},{5,6,0},{4,5,6}};
__constant__ int c_fs[6][3] = {{0,0,1},{0,1,0},{1,0,0},{2,0,0},{2,0,0},{2,0,0}}; // 0=b_up 1=clo 2=chi

__device__ __forceinline__ void ffma2(ull &d, const ull a, const ull b) {
    asm("fma.rn.f32x2 %0, %1, %2, %0;" : "+l"(d) : "l"(a), "l"(b));
}
__device__ __forceinline__ float2 u2f(ull v) {
    float2 r; asm("mov.b64 {%0,%1}, %2;" : "=f"(r.x), "=f"(r.y) : "l"(v)); return r;
}
__device__ __forceinline__ ull dup2(float v) {
    ull r; asm("mov.b64 %0, {%1,%1};" : "=l"(r) : "f"(v)); return r;
}

// ================= kA: F + WhT + Vp (independent stage-1 work) =================
__global__ void __launch_bounds__(256) kA(const void* idxraw, const float* __restrict__ cb,
                                          const float* __restrict__ sc,
                                          const float* __restrict__ Wh,
                                          const float* __restrict__ W_out,
                                          const float* __restrict__ b_out,
                                          const float* __restrict__ W_up) {
    __shared__ __align__(16) float su[7392];
    int bid = blockIdx.x, tid = threadIdx.x;

    if (bid < 128) {
        // ---- F[b][j][m] with inline int64/int32 detection ----
        const unsigned* w = (const unsigned*)idxraw;
        unsigned v = w[2 * tid + 1];
        int ok = (v == 0u) || (v == 0xFFFFFFFFu);
        int is64 = __syncthreads_and(ok);
        if (tid < 128) su[tid] = sc[tid];
        __syncthreads();
        int gt = bid * 256 + tid;
        int m = gt & 4095, gb = (gt >> 12) & 1, b = gt >> 13;
        float acc[8];
#pragma unroll
        for (int j = 0; j < 8; ++j) acc[j] = 0.f;
#pragma unroll
        for (int qq = 0; qq < 8; ++qq) {
            int gq = gb * 8 + qq;
            size_t off = (size_t)(b * 16 + gq) * 4096 + m;
            long long c;
            if (is64) c = ((const long long*)idxraw)[off];
            else      c = ((const int*)idxraw)[off];
            if (c >= 0) {
                const float4* row = (const float4*)(cb + ((size_t)gq * 1024 + (int)c) * 8);
                float4 r0 = row[0], r1 = row[1];
                const float* s = &su[gq * 8];
                acc[0] += r0.x*s[0]; acc[1] += r0.y*s[1];
                acc[2] += r0.z*s[2]; acc[3] += r0.w*s[3];
                acc[4] += r1.x*s[4]; acc[5] += r1.y*s[5];
                acc[6] += r1.z*s[6]; acc[7] += r1.w*s[7];
            }
        }
#pragma unroll
        for (int j = 0; j < 8; ++j)
            g_F[((size_t)b * 17 + gb * 8 + j) * 4096 + m] = acc[j];
        if (gb == 0) g_F[((size_t)b * 17 + 16) * 4096 + m] = 1.0f;

    } else if (bid < 640) {
        // ---- tiled transpose W_head [ho][co][u] -> WhT[u][co][ho] ----
        int t = bid - 128;
        int co0 = (t & 31) * 32, ho0 = (t >> 5) * 32;
        for (int p = tid; p < 1024; p += 256) {
            int ho_l = p >> 5, co_l = p & 31;
            const float* src = Wh + ((size_t)(ho0 + ho_l) * 1024 + co0 + co_l) * 7;
#pragma unroll
            for (int u = 0; u < 7; ++u) su[(u * 32 + co_l) * 33 + ho_l] = src[u];
        }
        __syncthreads();
        for (int p = tid; p < 7168; p += 256) {
            int u = p >> 10, r = p & 1023, co_l = r >> 5, ho_l = r & 31;
            g_WhT[((size_t)u * 1024 + co0 + co_l) * 512 + ho0 + ho_l] = su[(u * 32 + co_l) * 33 + ho_l];
        }

    } else {
        // ---- Vp[chunk][t][9][co]: partial over 16-wide c-chunk of P[j][c]*W_up[c][co][t]
        int t = bid - 640;                 // 256 blocks
        int cotile = t & 3, chunk = t >> 2; // chunk in [0,64)
        int co = cotile * 256 + tid;
        int g = chunk >> 5;
        int ebase = chunk * 16 - g * 512;
        if (tid < 144) {
            if (tid < 128) {
                int d = tid >> 4, ii = tid & 15;
                su[d * 16 + ii] = W_out[((size_t)(g * 8 + d)) * 512 + ebase + ii];
            } else {
                su[128 + (tid - 128)] = b_out[g * 512 + ebase + (tid - 128)];
            }
        }
        __syncthreads();
        float acc[4][9];
#pragma unroll
        for (int tt = 0; tt < 4; ++tt)
#pragma unroll
            for (int d = 0; d < 9; ++d) acc[tt][d] = 0.f;
#pragma unroll
        for (int i = 0; i < 16; ++i) {
            int c = chunk * 16 + i;
            float4 w4 = *(const float4*)&W_up[((size_t)c * 1024 + co) * 4];
            float wt[4] = {w4.x, w4.y, w4.z, w4.w};
#pragma unroll
            for (int d = 0; d < 8; ++d) {
                float p = su[d * 16 + i];
#pragma unroll
                for (int tt = 0; tt < 4; ++tt) acc[tt][d] += p * wt[tt];
            }
            float pb = su[128 + i];
#pragma unroll
            for (int tt = 0; tt < 4; ++tt) acc[tt][8] += pb * wt[tt];
        }
#pragma unroll
        for (int tt = 0; tt < 4; ++tt) {
#pragma unroll
            for (int d = 0; d < 8; ++d)
                g_Vp[(((size_t)chunk * 4 + tt) * 9 + d) * 1024 + co] = acc[tt][d];
            g_Vp[(((size_t)chunk * 4 + tt) * 9 + 8) * 1024 + co] = acc[tt][8];
        }
    }
}

// ================= kB: Vred (group-aware) =================
__global__ void __launch_bounds__(256) kB() {
    int idx = blockIdx.x * 256 + threadIdx.x;   // < 69632
    int row = idx >> 10, co = idx & 1023;
    int t = row / 17, j = row - t * 17;
    float s = 0.f;
    if (j == 16) {
#pragma unroll
        for (int cs = 0; cs < 64; ++cs)
            s += g_Vp[(((size_t)cs * 4 + t) * 9 + 8) * 1024 + co];
    } else if (j < 8) {
#pragma unroll
        for (int cs = 0; cs < 32; ++cs)
            s += g_Vp[(((size_t)cs * 4 + t) * 9 + j) * 1024 + co];
    } else {
#pragma unroll
        for (int cs = 32; cs < 64; ++cs)
            s += g_Vp[(((size_t)cs * 4 + t) * 9 + (j - 8)) * 1024 + co];
    }
    g_V[idx] = s;
}

// ================= kC: G-GEMM (f32x2-packed; 28 (u,t) pairs, s-grouped out) + corr1 ====
__global__ void __launch_bounds__(128) kC(const float* __restrict__ b_up) {
    __shared__ __align__(16) float sV2[128 * 80];   // [c][t*20 + j], 40KB
    int tid = threadIdx.x, bid = blockIdx.x;
    if (bid < 448) {
        int cs  = bid & 7;
        int hot = (bid >> 3) & 7;
        int u   = bid >> 6;              // 0..6
        int c0 = cs * 128, hb = hot * 64;
        int ho_l = tid & 31, rg = tid >> 5;   // rg = t
        for (int i = tid; i < 68 * 128; i += 128) {
            int row = i >> 7, c = i & 127;     // row = t*17+j
            int t = row / 17, j = row - t * 17;
            sV2[c * 80 + t * 20 + j] = g_V[(size_t)row * 1024 + c0 + c];
        }
        __syncthreads();
        ull acc2[9][2];
#pragma unroll
        for (int jj = 0; jj < 9; ++jj) { acc2[jj][0] = 0ull; acc2[jj][1] = 0ull; }
        const float* Wp = g_WhT + ((size_t)u * 1024 + c0) * 512 + hb + ho_l;
#pragma unroll 4
        for (int c = 0; c < 128; ++c) {
            float b0 = __ldg(&Wp[(size_t)c * 512]);
            float b1 = __ldg(&Wp[(size_t)c * 512 + 32]);
            ull b0d = dup2(b0), b1d = dup2(b1);
            const ull* av2 = (const ull*)&sV2[c * 80 + rg * 20];
#pragma unroll
            for (int jj = 0; jj < 9; ++jj) {
                ull av = av2[jj];
                ffma2(acc2[jj][0], av, b0d);
                ffma2(acc2[jj][1], av, b1d);
            }
        }
        int pidx = c_pidx[u][rg];
        float* gp = g_Gp + ((size_t)(cs * 28 + pidx) * 17) * 512 + hb + ho_l;
#pragma unroll
        for (int jj = 0; jj < 8; ++jj) {
            float2 x0 = u2f(acc2[jj][0]);
            float2 x1 = u2f(acc2[jj][1]);
            gp[(size_t)(2 * jj) * 512]          = x0.x;
            gp[(size_t)(2 * jj) * 512 + 32]     = x1.x;
            gp[(size_t)(2 * jj + 1) * 512]      = x0.y;
            gp[(size_t)(2 * jj + 1) * 512 + 32] = x1.y;
        }
        {
            float2 x0 = u2f(acc2[8][0]);
            float2 x1 = u2f(acc2[8][1]);
            gp[(size_t)16 * 512]      = x0.x;
            gp[(size_t)16 * 512 + 32] = x1.x;
        }
    } else {
        // corr1: 64 blocks of 128 threads
        int q = bid - 448;
        int b = q >> 4, r2 = q & 15, hi = r2 >> 3, cotile = r2 & 7;
        int co = cotile * 128 + tid;
        int frame = hi ? 4095 : 0;
        int t = hi ? 0 : 3;
        float acc = b_up[co];
#pragma unroll
        for (int j = 0; j < 17; ++j)
            acc += g_F[((size_t)b * 17 + j) * 4096 + frame] * g_V[((size_t)t * 17 + j) * 1024 + co];
        if (hi) g_chi[b * 1024 + co] = acc; else g_clo[b * 1024 + co] = acc;
    }
}

// ================= kD: K reduce (contiguous s-groups) + C9 (4x parallel) =========
__global__ void __launch_bounds__(512) kD(const float* __restrict__ b_up) {
    __shared__ float scoef[9][128];      // 4.6KB
    __shared__ float sred[4][9][128];    // 18KB
    int bid = blockIdx.x, tid = threadIdx.x;
    if (bid < 170) {
        int idx = bid * 512 + tid;     // 87040 exactly; s uniform per block
        int s = idx / 8704;
        int rem = idx - s * 8704;
        int p0 = c_pstart[s], np = c_np[s];
        float acc = 0.f;
#pragma unroll
        for (int p = 0; p < 4; ++p) {
            if (p < np) {
                size_t base = (size_t)(p0 + p) * 8704 + rem;
#pragma unroll
                for (int cs = 0; cs < 8; ++cs)
                    acc += g_Gp[(size_t)cs * (28 * 8704) + base];
            }
        }
        g_K[idx] = acc;
    } else {
        // C9: 224 blocks = u(7) x hot(4) x cq(8); 512 threads, csub covers 32 c's
        int v = bid - 170;
        int u = v >> 5, rem = v & 31;
        int hot = rem & 3, cq = rem >> 2;         // cq in [0,8)
        int hb = hot * 128;
        int ho_l = tid & 127, csub = tid >> 7;    // csub in [0,4)
        int cbase = cq * 128;
        for (int i = tid; i < 9 * 128; i += 512) {
            int k = i / 128, c = i & 127;
            int cg = cbase + c;
            float val;
            if (k == 0)      val = b_up[cg];
            else if (k < 5)  val = g_clo[(k - 1) * 1024 + cg];
            else             val = g_chi[(k - 5) * 1024 + cg];
            scoef[k][c] = val;
        }
        __syncthreads();
        int c0 = cbase + csub * 32;
        float acc[9];
#pragma unroll
        for (int k = 0; k < 9; ++k) acc[k] = 0.f;
        const float* W = g_WhT + ((size_t)u * 1024 + c0) * 512 + hb + ho_l;
#pragma unroll
        for (int cc = 0; cc < 32; ++cc) {
            float w = __ldg(&W[(size_t)cc * 512]);
#pragma unroll
            for (int k = 0; k < 9; ++k) acc[k] += scoef[k][csub * 32 + cc] * w;
        }
#pragma unroll
        for (int k = 0; k < 9; ++k) sred[csub][k][ho_l] = acc[k];
        __syncthreads();
        if (csub == 0) {
#pragma unroll
            for (int k = 0; k < 9; ++k) {
                float s = sred[0][k][ho_l] + sred[1][k][ho_l]
                        + sred[2][k][ho_l] + sred[3][k][ho_l];
                g_c9p[(((size_t)cq * 7 + u) * 9 + k) * 512 + hb + ho_l] = s;
            }
        }
    }
}

// ================= kE: main GEMM (f32x2), 32m x 128ho tile, 128 threads =========
// grid (128,4,4) = 2048 blocks, 2 CTAs/SM -> wave waste 1.2% (vs 15.6% at 1024 blocks)
// smem: sB [2*80*128]f @0 (81920B), sA2 [16*4tm*12]float2 @81920 (6144B), sFB2 [2*128]f @88064
__global__ void __launch_bounds__(128, 2) kE(float* __restrict__ out,
                                             const float* __restrict__ b_head) {
    extern __shared__ __align__(16) char smem_raw[];
    float*  sB   = (float*)smem_raw;                        // [r*80 + dm*16 + j][128]
    float2* sA2  = (float2*)(smem_raw + 81920);             // [j][tm 4][12]
    float*  sFB2 = (float*)(smem_raw + 81920 + 6144);       // [r][128]
    int tid = threadIdx.x;
    int mb = blockIdx.x * 32;
    int hb = blockIdx.y * 128;
    int b = blockIdx.z;
    // sB: vectorized float4 loads, 5120 float4 total
    {
        float4* sB4 = (float4*)sB;
#pragma unroll 8
        for (int i4 = tid; i4 < 5120; i4 += 128) {
            int q = i4 >> 5, hol4 = i4 & 31;
            int r = (q >= 80);
            int dmj = q - 80 * r;
            int dm = dmj >> 4, j = dmj & 15;
            int s = 2 * dm + (r ? 0 : 1);
            sB4[i4] = ((const float4*)(g_K + ((size_t)(s * 17 + j)) * 512 + hb))[hol4];
        }
    }
    for (int i = tid; i < 16 * 48; i += 128) {
        int j = i / 48, r = i % 48, tmw = r / 12, k = r % 12;
        int m = mb + tmw * 8 + k - 2;
        float v = (m >= 0 && m < 4096) ? g_F[((size_t)b * 17 + j) * 4096 + m] : 0.f;
        sA2[i] = make_float2(v, v);
    }
    // per-r fullbias: b_head + C9(k=0) + folded j=16 taps
    for (int i = tid; i < 256; i += 128) {
        int r = i >> 7, hol = i & 127;
        float s = b_head[hb + hol];
#pragma unroll
        for (int cs = 0; cs < 8; ++cs)
#pragma unroll
            for (int u = 0; u < 7; ++u)
                s += g_c9p[(((size_t)cs * 7 + u) * 9) * 512 + hb + hol];
#pragma unroll
        for (int dm = 0; dm < 5; ++dm) {
            int sv = 2 * dm + (r ? 0 : 1);
            s += g_K[((size_t)(sv * 17 + 16)) * 512 + hb + hol];
        }
        sFB2[r * 128 + hol] = s;
    }
    __syncthreads();

    int tho = tid & 31, tm = tid >> 5;   // tm in [0,4): 8 m each
    ull acc[2][2][8];
#pragma unroll
    for (int r = 0; r < 2; ++r)
#pragma unroll
        for (int h = 0; h < 2; ++h)
#pragma unroll
            for (int mi = 0; mi < 8; ++mi) acc[r][h][mi] = 0ull;

    const ull* uA = ((const ull*)sA2) + (size_t)tm * 12;
    const ull* uB = (const ull*)sB;     // rows of 64 ull (128 floats)

    for (int j = 0; j < 16; ++j) {
        ull a[12];
#pragma unroll
        for (int k = 0; k < 12; ++k) a[k] = uA[j * 48 + k];
#pragma unroll
        for (int dm = 0; dm < 5; ++dm) {
            int row0 = (dm * 16 + j) * 64;
            int row1 = (80 + dm * 16 + j) * 64;
            ull b00 = uB[row0 + tho];
            ull b01 = uB[row0 + 32 + tho];
            ull b10 = uB[row1 + tho];
            ull b11 = uB[row1 + 32 + tho];
#pragma unroll
            for (int mi = 0; mi < 8; ++mi) {
                ull av = a[mi + dm];
                ffma2(acc[0][0][mi], av, b00);
                ffma2(acc[0][1][mi], av, b01);
                ffma2(acc[1][0][mi], av, b10);
                ffma2(acc[1][1][mi], av, b11);
            }
        }
    }

    int nb = 2 * (mb + tm * 8);
#pragma unroll
    for (int h = 0; h < 2; ++h) {
        int hoA = hb + h * 64 + 2 * tho;
        float fbA0 = sFB2[h * 64 + 2 * tho];            // r=0, ho lane 0
        float fbA1 = sFB2[h * 64 + 2 * tho + 1];        // r=0, ho lane 1
        float fbB0 = sFB2[128 + h * 64 + 2 * tho];      // r=1, ho lane 0
        float fbB1 = sFB2[128 + h * 64 + 2 * tho + 1];  // r=1, ho lane 1
        float r0[16], r1[16];
#pragma unroll
        for (int mi = 0; mi < 8; ++mi) {
            float2 x0 = u2f(acc[0][h][mi]);   // r=0: {hoA, hoA+1}
            float2 x1 = u2f(acc[1][h][mi]);   // r=1
            r0[2 * mi]     = x0.x + fbA0;
            r0[2 * mi + 1] = x1.x + fbB0;
            r1[2 * mi]     = x0.y + fbA1;
            r1[2 * mi + 1] = x1.y + fbB1;
        }

        if (blockIdx.x == 0 && tm == 0) {
            // C9 spurious-term fix (n = 0,1,2)
#pragma unroll
            for (int ni = 0; ni < 3; ++ni) {
                float d0 = 0.f, d1 = 0.f;
                int nt = c_ncorr[ni];
#pragma unroll
                for (int k = 0; k < 3; ++k) {
                    if (k < nt) {
                        int u = c_fu[ni][k], src = c_fs[ni][k];
                        int kidx = (src == 0) ? 0 : (src == 1 ? 1 + b : 5 + b);
#pragma unroll
                        for (int cs = 0; cs < 8; ++cs) {
                            size_t o = (((size_t)cs * 7 + u) * 9 + kidx) * 512 + hoA;
                            d0 += g_c9p[o]; d1 += g_c9p[o + 1];
                        }
                    }
                }
                r0[ni] -= d0; r1[ni] -= d1;
            }
            // j16-fold missing-tap fix (window-clipped columns q=0..3)
            float K16_0a = g_K[(size_t)(0 * 17 + 16) * 512 + hoA], K16_0b = g_K[(size_t)(0 * 17 + 16) * 512 + hoA + 1];
            float K16_1a = g_K[(size_t)(1 * 17 + 16) * 512 + hoA], K16_1b = g_K[(size_t)(1 * 17 + 16) * 512 + hoA + 1];
            float K16_2a = g_K[(size_t)(2 * 17 + 16) * 512 + hoA], K16_2b = g_K[(size_t)(2 * 17 + 16) * 512 + hoA + 1];
            float K16_3a = g_K[(size_t)(3 * 17 + 16) * 512 + hoA], K16_3b = g_K[(size_t)(3 * 17 + 16) * 512 + hoA + 1];
            r0[0] -= K16_1a + K16_3a;  r1[0] -= K16_1b + K16_3b;   // m0=0, r=0
            r0[1] -= K16_0a + K16_2a;  r1[1] -= K16_0b + K16_2b;   // m0=0, r=1
            r0[2] -= K16_1a;           r1[2] -= K16_1b;            // m0=1, r=0
            r0[3] -= K16_0a;           r1[3] -= K16_0b;            // m0=1, r=1
        }
        if (blockIdx.x == 127 && tm == 3) {
            // C9 spurious-term fix (n = 8189,8190,8191)
#pragma unroll
            for (int ni = 3; ni < 6; ++ni) {
                float d0 = 0.f, d1 = 0.f;
                int nt = c_ncorr[ni];
#pragma unroll
                for (int k = 0; k < 3; ++k) {
                    if (k < nt) {
                        int u = c_fu[ni][k], src = c_fs[ni][k];
                        int kidx = (src == 0) ? 0 : (src == 1 ? 1 + b : 5 + b);
#pragma unroll
                        for (int cs = 0; cs < 8; ++cs) {
                            size_t o = (((size_t)cs * 7 + u) * 9 + kidx) * 512 + hoA;
                            d0 += g_c9p[o]; d1 += g_c9p[o + 1];
                        }
                    }
                }
                r0[ni + 10] -= d0; r1[ni + 10] -= d1;
            }
            // j16-fold missing-tap fix (q=12..15 -> n=8188..8191)
            float K16_6a = g_K[(size_t)(6 * 17 + 16) * 512 + hoA], K16_6b = g_K[(size_t)(6 * 17 + 16) * 512 + hoA + 1];
            float K16_7a = g_K[(size_t)(7 * 17 + 16) * 512 + hoA], K16_7b = g_K[(size_t)(7 * 17 + 16) * 512 + hoA + 1];
            float K16_8a = g_K[(size_t)(8 * 17 + 16) * 512 + hoA], K16_8b = g_K[(size_t)(8 * 17 + 16) * 512 + hoA + 1];
            float K16_9a = g_K[(size_t)(9 * 17 + 16) * 512 + hoA], K16_9b = g_K[(size_t)(9 * 17 + 16) * 512 + hoA + 1];
            r0[12] -= K16_9a;           r1[12] -= K16_9b;           // m0=4094, r=0
            r0[13] -= K16_8a;           r1[13] -= K16_8b;           // m0=4094, r=1
            r0[14] -= K16_7a + K16_9a;  r1[14] -= K16_7b + K16_9b;  // m0=4095, r=0
            r0[15] -= K16_6a + K16_8a;  r1[15] -= K16_6b + K16_8b;  // m0=4095, r=1
        }

        float* p0 = out + ((size_t)b * 512 + hoA) * 8192 + nb;
        float* p1 = p0 + 8192;
#pragma unroll
        for (int s = 0; s < 4; ++s) {
            *(float4*)(p0 + 4 * s) = *(float4*)&r0[4 * s];
            *(float4*)(p1 + 4 * s) = *(float4*)&r1[4 * s];
        }
    }
}

// ================= host =================
extern "C" void kernel_launch(void* const* d_in, const int* in_sizes, int n_in,
                              void* d_out, int out_size) {
    const void*  idx    = d_in[0];
    const float* cb     = (const float*)d_in[1];
    const float* sc     = (const float*)d_in[2];
    const float* W_out  = (const float*)d_in[3];
    const float* b_out  = (const float*)d_in[4];
    const float* W_up   = (const float*)d_in[5];
    const float* b_up   = (const float*)d_in[6];
    const float* W_head = (const float*)d_in[7];
    const float* b_head = (const float*)d_in[8];
    float* out = (float*)d_out;

    const int KE_SMEM = 81920 + 6144 + 1024;
    cudaFuncSetAttribute(kE, cudaFuncAttributeMaxDynamicSharedMemorySize, KE_SMEM);

    kA<<<896, 256>>>(idx, cb, sc, W_head, W_out, b_out, W_up);
    kB<<<272, 256>>>();
    kC<<<512, 128>>>(b_up);
    kD<<<394, 512>>>(b_up);
    kE<<<dim3(128, 4, 4), 128, KE_SMEM>>>(out, b_head);
}